// round 2
// baseline (speedup 1.0000x reference)
#include <cuda_runtime.h>
#include <math.h>

// Problem constants
#define B_   4
#define H_   256
#define W_   256
#define CI   64
#define CM   512
#define NA   9

// Tiling
#define TH   8          // tile height (rows)
#define TW   16         // tile width  (cols)
#define CB   16         // mid-channel block
#define WSTR 580        // padded per-channel weight stride (floats), %4==0 for float4, odd/32-friendly

// Dynamic smem layout (floats):
//   xs4  : 16 ci4-groups x 10 rows x 18 cols  (float4)  = 2880 float4 = 11520 floats
//   ws   : CB x WSTR                                    =  9280 floats
//   wcat : CB x 48                                      =   768 floats
//   feats: CB x 128                                     =  2048 floats
// total = 23616 floats = 94464 bytes  -> 2 blocks/SM
#define SMEM_FLOATS 23616
#define SMEM_BYTES  (SMEM_FLOATS * 4)

__global__ __launch_bounds__(128, 2)
void rpn_fused_kernel(const float* __restrict__ x,
                      const float* __restrict__ w_base,
                      const float* __restrict__ b_base,
                      const float* __restrict__ w_cls,
                      const float* __restrict__ b_cls,
                      const float* __restrict__ w_reg,
                      const float* __restrict__ b_reg,
                      float* __restrict__ out)
{
    extern __shared__ float smem[];
    float4* xs4   = (float4*)smem;                    // [ci4][y][x] : [16][10][18]
    float*  ws    = smem + 11520;                     // [CB][WSTR]
    float*  wcat  = ws + CB * WSTR;                   // [CB][48] (0..8 cls, 9..44 reg, pad)
    float*  feats = wcat + CB * 48;                   // [CB][128]

    const int tid = threadIdx.x;
    const int bid = blockIdx.x;
    const int b   = bid >> 9;          // 512 tiles per image (32 y-tiles * 16 x-tiles)
    const int tno = bid & 511;
    const int ty  = tno >> 4;          // 0..31
    const int tx  = tno & 15;          // 0..15
    const int gy0 = ty * TH;
    const int gx0 = tx * TW;

    // ---- Load x window [10][18][64] into xs4[ci4][y][x] (zero-padded SAME borders) ----
    const float* xb = x + (long)b * H_ * W_ * CI;
    for (int e = tid; e < 16 * 10 * 18; e += 128) {
        int ci4 = e & 15;
        int rem = e >> 4;
        int xx  = rem % 18;
        int yy  = rem / 18;
        int gy  = gy0 + yy - 1;
        int gx  = gx0 + xx - 1;
        float4 v = make_float4(0.f, 0.f, 0.f, 0.f);
        if ((unsigned)gy < (unsigned)H_ && (unsigned)gx < (unsigned)W_) {
            v = *(const float4*)(xb + ((long)gy * W_ + gx) * CI + ci4 * 4);
        }
        xs4[ci4 * 180 + yy * 18 + xx] = v;
    }

    // Thread roles
    const int cg = tid >> 5;   // warp id -> channel group (4 channels), warp-uniform
    const int pg = tid & 31;   // position group: positions pg, pg+32, pg+64, pg+96
    const int x0 = pg & 15;
    const int y0 = pg >> 4;

    // Persistent per-position output accumulators (48, 45 used) — constant-indexed, stays in regs
    float acc[48];
    #pragma unroll
    for (int j = 0; j < 48; j++) acc[j] = 0.f;

    for (int cb = 0; cb < CM; cb += CB) {
        __syncthreads();   // protect ws/wcat from previous stage B readers (and xs on iter 0)

        // ---- Cooperative load: transposed base weights ws[ch][k], k in [0,576) ----
        for (int e = tid; e < CB * 576; e += 128) {
            int ch = e & 15;
            int k  = e >> 4;
            ws[ch * WSTR + k] = w_base[(long)k * CM + cb + ch];
        }
        // ---- 1x1 head weights: wcat[ch][0..8]=cls, [9..44]=reg, pad zeros ----
        for (int e = tid; e < CB * 48; e += 128) {
            int ch = e / 48;
            int j  = e % 48;
            int c  = cb + ch;
            float v = 0.f;
            if (j < 9)       v = w_cls[c * NA + j];
            else if (j < 45) v = w_reg[c * 36 + (j - 9)];
            wcat[ch * 48 + j] = v;
        }
        __syncthreads();

        // ---- Stage A: 4 positions x 4 channels register microkernel over K=576 ----
        float facc[4][4];
        #pragma unroll
        for (int c = 0; c < 4; c++)
            #pragma unroll
            for (int p = 0; p < 4; p++) facc[c][p] = 0.f;

        #pragma unroll 1
        for (int ky = 0; ky < 3; ky++) {
            #pragma unroll 1
            for (int kx = 0; kx < 3; kx++) {
                const float4* xrow = xs4 + (y0 + ky) * 18 + (x0 + kx);
                const float*  wk   = ws + cg * 4 * WSTR + (ky * 3 + kx) * 64;
                #pragma unroll 4
                for (int ci4 = 0; ci4 < 16; ci4++) {
                    float4 xv[4];
                    #pragma unroll
                    for (int p = 0; p < 4; p++)
                        xv[p] = xrow[ci4 * 180 + p * 36];   // rows y0, y0+2, y0+4, y0+6
                    #pragma unroll
                    for (int c = 0; c < 4; c++) {
                        float4 wv = *(const float4*)(wk + c * WSTR + ci4 * 4); // warp-broadcast
                        #pragma unroll
                        for (int p = 0; p < 4; p++) {
                            facc[c][p] = fmaf(xv[p].x, wv.x, facc[c][p]);
                            facc[c][p] = fmaf(xv[p].y, wv.y, facc[c][p]);
                            facc[c][p] = fmaf(xv[p].z, wv.z, facc[c][p]);
                            facc[c][p] = fmaf(xv[p].w, wv.w, facc[c][p]);
                        }
                    }
                }
            }
        }

        // bias + relu -> feats[ch][pos]
        #pragma unroll
        for (int c = 0; c < 4; c++) {
            float bb = __ldg(&b_base[cb + cg * 4 + c]);
            #pragma unroll
            for (int p = 0; p < 4; p++) {
                float f = facc[c][p] + bb;
                feats[(cg * 4 + c) * 128 + pg + 32 * p] = fmaxf(f, 0.f);
            }
        }
        __syncthreads();

        // ---- Stage B: each thread owns position `tid`, accumulates 45 outputs ----
        #pragma unroll 4
        for (int ch = 0; ch < CB; ch++) {
            float f = feats[ch * 128 + tid];
            const float4* wc = (const float4*)(wcat + ch * 48);
            #pragma unroll
            for (int j = 0; j < 12; j++) {
                float4 wv = wc[j];                       // warp-broadcast
                acc[4 * j + 0] = fmaf(f, wv.x, acc[4 * j + 0]);
                acc[4 * j + 1] = fmaf(f, wv.y, acc[4 * j + 1]);
                acc[4 * j + 2] = fmaf(f, wv.z, acc[4 * j + 2]);
                acc[4 * j + 3] = fmaf(f, wv.w, acc[4 * j + 3]);
            }
        }
    }

    // ---- Epilogue: sigmoid scores, threshold-masked deltas ----
    const int ly = tid >> 4;
    const int lx = tid & 15;
    const int gy = gy0 + ly;
    const int gx = gx0 + lx;
    float* o = out + (((long)b * H_ + gy) * W_ + gx) * 45;

    float sc[9];
    #pragma unroll
    for (int j = 0; j < 9; j++) {
        float z = acc[j] + __ldg(&b_cls[j]);
        sc[j] = 1.f / (1.f + __expf(-z));
        o[j] = sc[j];
    }
    #pragma unroll
    for (int an = 0; an < 9; an++) {
        float m = sc[an] > 0.7f ? 1.f : 0.f;
        #pragma unroll
        for (int i = 0; i < 4; i++) {
            int j = 9 + an * 4 + i;
            o[j] = (acc[j] + __ldg(&b_reg[an * 4 + i])) * m;
        }
    }
}

extern "C" void kernel_launch(void* const* d_in, const int* in_sizes, int n_in,
                              void* d_out, int out_size)
{
    const float* x      = (const float*)d_in[0];
    const float* w_base = (const float*)d_in[1];
    const float* b_base = (const float*)d_in[2];
    const float* w_cls  = (const float*)d_in[3];
    const float* b_cls  = (const float*)d_in[4];
    const float* w_reg  = (const float*)d_in[5];
    const float* b_reg  = (const float*)d_in[6];
    float* out = (float*)d_out;

    // Not a stream op — safe under graph capture; idempotent every call.
    cudaFuncSetAttribute(rpn_fused_kernel,
                         cudaFuncAttributeMaxDynamicSharedMemorySize, SMEM_BYTES);

    // 4 images * 32 y-tiles * 16 x-tiles = 2048 blocks
    rpn_fused_kernel<<<2048, 128, SMEM_BYTES>>>(
        x, w_base, b_base, w_cls, b_cls, w_reg, b_reg, out);
}

// round 4
// speedup vs baseline: 6.4430x; 6.4430x over previous
#include <cuda_runtime.h>
#include <cuda_bf16.h>
#include <stdint.h>

// ---------------- device globals (pre-converted data) ----------------
__device__ __align__(16) __nv_bfloat16 g_xhi[4 * 256 * 256 * 64];
__device__ __align__(16) __nv_bfloat16 g_xlo[4 * 256 * 256 * 64];
__device__ __align__(16) uint32_t g_wt[72 * 4096];  // [kk*8+cb]: hi 2048 u32 | lo 2048, [n=64][k=64] swizzled
__device__ __align__(16) uint32_t g_wh[8 * 3072];   // [cb]: hi 1536 | lo 1536, [n=48][k=64] swizzled

__device__ __forceinline__ uint32_t pack2(float a, float b, float* ra, float* rb) {
    __nv_bfloat16 ha = __float2bfloat16(a), hb = __float2bfloat16(b);
    *ra = a - __bfloat162float(ha);
    *rb = b - __bfloat162float(hb);
    return (uint32_t)__bfloat16_as_ushort(ha) | ((uint32_t)__bfloat16_as_ushort(hb) << 16);
}
__device__ __forceinline__ uint32_t packh(float a, float b) {
    return (uint32_t)__bfloat16_as_ushort(__float2bfloat16(a)) |
           ((uint32_t)__bfloat16_as_ushort(__float2bfloat16(b)) << 16);
}

// ---------------- prologue: split x, convert+swizzle weights ----------------
// swizzle: within each 128B row (64 bf16, 8 chunks of 16B), chunk' = chunk ^ (row & 7)
__global__ void prep_kernel(const float* __restrict__ x, const float* __restrict__ wb,
                            const float* __restrict__ wc, const float* __restrict__ wr) {
    int gid = blockIdx.x * 256 + threadIdx.x;
    if (gid < 4194304) {                       // x: one float4 -> 4 bf16 hi + 4 lo
        float4 v = ((const float4*)x)[gid];
        float r0, r1;
        uint32_t h0 = pack2(v.x, v.y, &r0, &r1);
        uint32_t l0 = packh(r0, r1);
        uint32_t h1 = pack2(v.z, v.w, &r0, &r1);
        uint32_t l1 = packh(r0, r1);
        ((uint2*)g_xhi)[gid] = make_uint2(h0, h1);
        ((uint2*)g_xlo)[gid] = make_uint2(l0, l1);
    } else if (gid < 4194304 + 147456) {       // trunk weights -> [t][n=64][k=64]
        int e = gid - 4194304;
        int t = e >> 11, idx = e & 2047;       // t = kk*8+cb
        int kk = t >> 3, cb = t & 7;
        int n = idx >> 5, kw = idx & 31;       // kw = k/2
        int k = kw * 2;
        const float* ws = wb + ((size_t)kk * 64 + k) * 512 + cb * 64 + n;
        float f0 = ws[0], f1 = ws[512];
        float r0, r1;
        uint32_t hi = pack2(f0, f1, &r0, &r1);
        uint32_t lo = packh(r0, r1);
        uint32_t sidx = (uint32_t)n * 32 + ((((uint32_t)kw >> 2) ^ (n & 7)) << 2) + (kw & 3);
        g_wt[t * 4096 + sidx] = hi;
        g_wt[t * 4096 + 2048 + sidx] = lo;
    } else if (gid < 4194304 + 147456 + 12288) {  // head weights -> [cb][n=48][k=64]
        int e = gid - 4194304 - 147456;
        int cb = e / 1536, idx = e - cb * 1536;
        int n = idx >> 5, kw = idx & 31;
        int k = kw * 2;
        int c0 = cb * 64 + k;
        float f0 = 0.f, f1 = 0.f;
        if (n < 9)       { f0 = wc[c0 * 9 + n];      f1 = wc[(c0 + 1) * 9 + n]; }
        else if (n < 45) { f0 = wr[c0 * 36 + n - 9]; f1 = wr[(c0 + 1) * 36 + n - 9]; }
        float r0, r1;
        uint32_t hi = pack2(f0, f1, &r0, &r1);
        uint32_t lo = packh(r0, r1);
        uint32_t sidx = (uint32_t)n * 32 + ((((uint32_t)kw >> 2) ^ (n & 7)) << 2) + (kw & 3);
        g_wh[cb * 3072 + sidx] = hi;
        g_wh[cb * 3072 + 1536 + sidx] = lo;
    }
}

// ---------------- warp-MMA plumbing (all sm_80+, plain-target safe) ----------------
__device__ __forceinline__ uint32_t smem_u32(const void* p) {
    uint32_t a;
    asm("{ .reg .u64 t; cvta.to.shared.u64 t, %1; cvt.u32.u64 %0, t; }" : "=r"(a) : "l"(p));
    return a;
}
__device__ __forceinline__ void ldsm4(uint32_t* r, uint32_t addr) {
    asm volatile("ldmatrix.sync.aligned.m8n8.x4.shared.b16 {%0,%1,%2,%3}, [%4];"
                 : "=r"(r[0]), "=r"(r[1]), "=r"(r[2]), "=r"(r[3]) : "r"(addr));
}
__device__ __forceinline__ void mma16816(float* d, const uint32_t* a, uint32_t b0, uint32_t b1) {
    asm volatile("mma.sync.aligned.m16n8k16.row.col.f32.bf16.bf16.f32 "
                 "{%0,%1,%2,%3}, {%4,%5,%6,%7}, {%8,%9}, {%0,%1,%2,%3};"
                 : "+f"(d[0]), "+f"(d[1]), "+f"(d[2]), "+f"(d[3])
                 : "r"(a[0]), "r"(a[1]), "r"(a[2]), "r"(a[3]), "r"(b0), "r"(b1));
}
#define CP16(dst, src) asm volatile("cp.async.cg.shared.global [%0], [%1], 16;" :: "r"(dst), "l"(src) : "memory")
#define CP_COMMIT()    asm volatile("cp.async.commit_group;" ::: "memory")
#define CP_WAIT()      asm volatile("cp.async.wait_all;" ::: "memory")

__device__ __forceinline__ uint32_t pk(float v0, float v1) {   // low16 = v0
    uint32_t r;
    asm("cvt.rn.bf16x2.f32 %0, %1, %2;" : "=r"(r) : "f"(v1), "f"(v0));
    return r;
}

// ---------------- SMEM layout ----------------
#define SM_WHI  0            // 180 rows x 128B = 23040
#define SM_WLO  23040
#define SM_B    46080        // 2 x (hi 8192 | lo 8192) = 32768
#define SM_HB   78848        // hi 6144 | lo 6144 = 12288
#define SM_BIAS 91136        // 64 floats
#define SMEM_BYTES 91392

__global__ __launch_bounds__(128, 2)
void rpn_mma_kernel(const float* __restrict__ b_base, const float* __restrict__ b_cls,
                    const float* __restrict__ b_reg, float* __restrict__ out)
{
    extern __shared__ unsigned char smem[];
    const uint32_t sb = smem_u32(smem);
    const int tid = threadIdx.x, wid = tid >> 5, lane = tid & 31;
    const int bid = blockIdx.x;
    const int b = bid >> 9;
    const int tno = bid & 511;
    const int gy0 = (tno >> 4) * 8, gx0 = (tno & 15) * 16;

    // ---- input window 10x18x64 (hi+lo bf16), chunk-xor swizzled ----
    const uint4* xh = (const uint4*)g_xhi + (size_t)b * 524288;
    const uint4* xl = (const uint4*)g_xlo + (size_t)b * 524288;
    uint32_t* whi = (uint32_t*)(smem + SM_WHI);
    uint32_t* wlo = (uint32_t*)(smem + SM_WLO);
    for (int e = tid; e < 1440; e += 128) {
        int r = e >> 3, c8 = e & 7;
        int wy = r / 18, wx = r - wy * 18;
        int gy = gy0 - 1 + wy, gx = gx0 - 1 + wx;
        uint4 vh = make_uint4(0, 0, 0, 0), vl = vh;
        if ((unsigned)gy < 256u && (unsigned)gx < 256u) {
            size_t si = (size_t)(gy * 256 + gx) * 8 + c8;
            vh = xh[si]; vl = xl[si];
        }
        uint32_t di = (uint32_t)r * 32 + (uint32_t)((c8 ^ (r & 7)) << 2);
        *(uint4*)(whi + di) = vh;
        *(uint4*)(wlo + di) = vl;
    }

    // per-lane ldmatrix invariants
    const int rowA  = ((lane >> 3) & 1) * 8 + (lane & 7); // A matrix row / B n-row base
    const int kc    = lane >> 4;                          // k-chunk select
    const int g     = lane >> 2, tg = lane & 3;

    float hacc[2][6][4];
    #pragma unroll
    for (int mt = 0; mt < 2; mt++)
        #pragma unroll
        for (int nt = 0; nt < 6; nt++)
            #pragma unroll
            for (int q = 0; q < 4; q++) hacc[mt][nt][q] = 0.f;

    #pragma unroll 1
    for (int cb = 0; cb < 8; cb++) {
        __syncthreads();   // prior head-B reads / buf0 reads complete
        {   // head-B + tap0-B copies + bias
            const uint4* s1 = (const uint4*)(g_wh + cb * 3072);
            #pragma unroll
            for (int i = 0; i < 6; i++)
                CP16(sb + SM_HB + (tid + 128 * i) * 16, s1 + tid + 128 * i);
            const uint4* s2 = (const uint4*)(g_wt + (size_t)cb * 4096);
            #pragma unroll
            for (int i = 0; i < 8; i++)
                CP16(sb + SM_B + (tid + 128 * i) * 16, s2 + tid + 128 * i);
            CP_COMMIT();
            if (tid < 64) *(float*)(smem + SM_BIAS + tid * 4) = b_base[cb * 64 + tid];
        }
        CP_WAIT();
        __syncthreads();

        float acc[2][8][4];
        #pragma unroll
        for (int mt = 0; mt < 2; mt++)
            #pragma unroll
            for (int nt = 0; nt < 8; nt++)
                #pragma unroll
                for (int q = 0; q < 4; q++) acc[mt][nt][q] = 0.f;

        #pragma unroll 1
        for (int kk = 0; kk < 9; kk++) {
            const int s = kk & 1;
            if (kk < 8) {   // prefetch next tap's B into the other buffer
                const uint4* s2 = (const uint4*)(g_wt + (size_t)((kk + 1) * 8 + cb) * 4096);
                uint32_t dst = sb + SM_B + (s ^ 1) * 16384;
                #pragma unroll
                for (int i = 0; i < 8; i++)
                    CP16(dst + (tid + 128 * i) * 16, s2 + tid + 128 * i);
                CP_COMMIT();
            }
            const int ky = kk / 3, kx = kk - 3 * ky;
            const uint32_t sB = sb + SM_B + s * 16384;

            #pragma unroll
            for (int ks = 0; ks < 4; ks++) {
                uint32_t ah[2][4], al[2][4];
                #pragma unroll
                for (int mt = 0; mt < 2; mt++) {
                    int r = (wid * 2 + mt + ky) * 18 + rowA + kx;
                    uint32_t off = (uint32_t)r * 128 + (uint32_t)(((ks * 2 + kc) ^ (r & 7)) << 4);
                    ldsm4(ah[mt], sb + SM_WHI + off);
                    ldsm4(al[mt], sb + SM_WLO + off);
                }
                #pragma unroll
                for (int np = 0; np < 4; np++) {
                    uint32_t offb = (uint32_t)(np * 16 + rowA) * 128 +
                                    (uint32_t)(((ks * 2 + kc) ^ (rowA & 7)) << 4);
                    uint32_t bh[4], bl[4];
                    ldsm4(bh, sB + offb);
                    ldsm4(bl, sB + 8192 + offb);
                    #pragma unroll
                    for (int mt = 0; mt < 2; mt++) {
                        mma16816(acc[mt][2 * np],     ah[mt], bh[0], bh[2]);  // hh
                        mma16816(acc[mt][2 * np],     al[mt], bh[0], bh[2]);  // lh
                        mma16816(acc[mt][2 * np],     ah[mt], bl[0], bl[2]);  // hl
                        mma16816(acc[mt][2 * np + 1], ah[mt], bh[1], bh[3]);
                        mma16816(acc[mt][2 * np + 1], al[mt], bh[1], bh[3]);
                        mma16816(acc[mt][2 * np + 1], ah[mt], bl[1], bl[3]);
                    }
                }
            }
            CP_WAIT();
            __syncthreads();
        }

        // ---- head: A frags straight from trunk accumulators ----
        const float* bias = (const float*)(smem + SM_BIAS);
        float bb[8][2];
        #pragma unroll
        for (int j = 0; j < 8; j++) {
            bb[j][0] = bias[8 * j + 2 * tg];
            bb[j][1] = bias[8 * j + 2 * tg + 1];
        }
        #pragma unroll
        for (int hk = 0; hk < 4; hk++) {
            uint32_t hA[2][4], lA[2][4];
            #pragma unroll
            for (int mt = 0; mt < 2; mt++) {
                #pragma unroll
                for (int q = 0; q < 4; q++) {
                    int j  = 2 * hk + (q >> 1);
                    int d0 = (q & 1) * 2;
                    float v0 = fmaxf(acc[mt][j][d0]     + bb[j][0], 0.f);
                    float v1 = fmaxf(acc[mt][j][d0 + 1] + bb[j][1], 0.f);
                    float h0 = __bfloat162float(__float2bfloat16(v0));
                    float h1 = __bfloat162float(__float2bfloat16(v1));
                    hA[mt][q] = pk(v0, v1);
                    lA[mt][q] = pk(v0 - h0, v1 - h1);
                }
            }
            #pragma unroll
            for (int np = 0; np < 3; np++) {
                uint32_t offb = (uint32_t)(np * 16 + rowA) * 128 +
                                (uint32_t)(((hk * 2 + kc) ^ (rowA & 7)) << 4);
                uint32_t bh[4], bl[4];
                ldsm4(bh, sb + SM_HB + offb);
                ldsm4(bl, sb + SM_HB + 6144 + offb);
                #pragma unroll
                for (int mt = 0; mt < 2; mt++) {
                    mma16816(hacc[mt][2 * np],     hA[mt], bh[0], bh[2]);
                    mma16816(hacc[mt][2 * np],     lA[mt], bh[0], bh[2]);
                    mma16816(hacc[mt][2 * np],     hA[mt], bl[0], bl[2]);
                    mma16816(hacc[mt][2 * np + 1], hA[mt], bh[1], bh[3]);
                    mma16816(hacc[mt][2 * np + 1], lA[mt], bh[1], bh[3]);
                    mma16816(hacc[mt][2 * np + 1], hA[mt], bl[1], bl[3]);
                }
            }
        }
    }

    // ---- epilogue: stage head results, then per-position sigmoid/mask ----
    __syncthreads();
    float* feat = (float*)smem;   // [128][48]
    #pragma unroll
    for (int mt = 0; mt < 2; mt++) {
        int p0 = wid * 32 + mt * 16 + g;
        #pragma unroll
        for (int nt = 0; nt < 6; nt++) {
            int c = 8 * nt + 2 * tg;
            feat[p0 * 48 + c]           = hacc[mt][nt][0];
            feat[p0 * 48 + c + 1]       = hacc[mt][nt][1];
            feat[(p0 + 8) * 48 + c]     = hacc[mt][nt][2];
            feat[(p0 + 8) * 48 + c + 1] = hacc[mt][nt][3];
        }
    }
    __syncthreads();
    {
        int y = gy0 + (tid >> 4), xo = gx0 + (tid & 15);
        float* o = out + (((size_t)b * 256 + y) * 256 + xo) * 45;
        const float* f = feat + tid * 48;
        float sc[9];
        #pragma unroll
        for (int j = 0; j < 9; j++) {
            float z = f[j] + __ldg(b_cls + j);
            sc[j] = 1.f / (1.f + __expf(-z));
            o[j] = sc[j];
        }
        #pragma unroll
        for (int an = 0; an < 9; an++) {
            float msk = sc[an] > 0.7f ? 1.f : 0.f;
            #pragma unroll
            for (int i = 0; i < 4; i++)
                o[9 + an * 4 + i] = (f[9 + an * 4 + i] + __ldg(b_reg + an * 4 + i)) * msk;
        }
    }
}

extern "C" void kernel_launch(void* const* d_in, const int* in_sizes, int n_in,
                              void* d_out, int out_size)
{
    const float* x      = (const float*)d_in[0];
    const float* w_base = (const float*)d_in[1];
    const float* b_base = (const float*)d_in[2];
    const float* w_cls  = (const float*)d_in[3];
    const float* b_cls  = (const float*)d_in[4];
    const float* w_reg  = (const float*)d_in[5];
    const float* b_reg  = (const float*)d_in[6];

    cudaFuncSetAttribute(rpn_mma_kernel,
                         cudaFuncAttributeMaxDynamicSharedMemorySize, SMEM_BYTES);

    prep_kernel<<<17008, 256>>>(x, w_base, w_cls, w_reg);
    rpn_mma_kernel<<<2048, 128, SMEM_BYTES>>>(b_base, b_cls, b_reg, (float*)d_out);
}